// round 1
// baseline (speedup 1.0000x reference)
#include <cuda_runtime.h>

#define N_LAYERS 32
#define N_SUB    8
#define TPB      256
#define EPT      4

__device__ __forceinline__ float tanh_fast(float x) {
    float y;
    asm("tanh.approx.f32 %0, %1;" : "=f"(y) : "f"(x));
    return y;
}

__global__ __launch_bounds__(TPB)
void sympnet_kernel(const float2* __restrict__ x,
                    const float*  __restrict__ act_w,
                    const float*  __restrict__ bias_b,
                    const float*  __restrict__ lin_w,
                    float2*       __restrict__ out,
                    int n)
{
    // Per-layer affine maps: forward (bias then 8 shears composed) and its exact inverse.
    __shared__ float s_fwd[N_LAYERS][6];   // m00,m01,m10,m11,c0,c1
    __shared__ float s_inv[N_LAYERS][6];
    __shared__ float s_aw[N_LAYERS];

    const int t = threadIdx.x;

    if (t < N_LAYERS) {
        // forward composition for layer t: state s = M*v + c, v = post-activation state
        const int i = t;
        float m00 = 1.f, m01 = 0.f, m10 = 0.f, m11 = 1.f;
        float c0 = bias_b[2 * i + 0];
        float c1 = bias_b[2 * i + 1];
        #pragma unroll
        for (int j = 0; j < N_SUB; ++j) {
            float w = lin_w[i * N_SUB + j];
            if ((j & 1) == 0) {          // q += w*p
                m00 = fmaf(w, m10, m00);
                m01 = fmaf(w, m11, m01);
                c0  = fmaf(w, c1,  c0);
            } else {                      // p += w*q
                m10 = fmaf(w, m00, m10);
                m11 = fmaf(w, m01, m11);
                c1  = fmaf(w, c0,  c1);
            }
        }
        s_fwd[i][0] = m00; s_fwd[i][1] = m01;
        s_fwd[i][2] = m10; s_fwd[i][3] = m11;
        s_fwd[i][4] = c0;  s_fwd[i][5] = c1;
    } else if (t < 2 * N_LAYERS) {
        // inverse composition for layer i: reversed shears (negated), then bias subtract
        const int i = t - N_LAYERS;
        float u00 = 1.f, u01 = 0.f, u10 = 0.f, u11 = 1.f;
        float d0 = 0.f, d1 = 0.f;
        #pragma unroll
        for (int j = N_SUB - 1; j >= 0; --j) {
            float w = lin_w[i * N_SUB + j];
            if ((j & 1) == 0) {          // q -= w*p
                u00 = fmaf(-w, u10, u00);
                u01 = fmaf(-w, u11, u01);
                d0  = fmaf(-w, d1,  d0);
            } else {                      // p -= w*q
                u10 = fmaf(-w, u00, u10);
                u11 = fmaf(-w, u01, u11);
                d1  = fmaf(-w, d0,  d1);
            }
        }
        d0 -= bias_b[2 * i + 0];
        d1 -= bias_b[2 * i + 1];
        s_inv[i][0] = u00; s_inv[i][1] = u01;
        s_inv[i][2] = u10; s_inv[i][3] = u11;
        s_inv[i][4] = d0;  s_inv[i][5] = d1;
    } else if (t < 2 * N_LAYERS + N_LAYERS) {
        s_aw[t - 2 * N_LAYERS] = act_w[t - 2 * N_LAYERS];
    }
    __syncthreads();

    const int base = blockIdx.x * (TPB * EPT) + t;

    float q[EPT], p[EPT];
    #pragma unroll
    for (int e = 0; e < EPT; ++e) {
        int idx = base + e * TPB;
        if (idx < n) {
            float2 v = x[idx];
            q[e] = v.x; p[e] = v.y;
        } else {
            q[e] = 0.f; p[e] = 0.f;
        }
    }

    // ---------------- forward chain ----------------
    #pragma unroll
    for (int i = 0; i < N_LAYERS; i += 2) {
        // layer i (even): q += aw*tanh(p), then affine
        {
            float aw = s_aw[i];
            float m00 = s_fwd[i][0], m01 = s_fwd[i][1];
            float m10 = s_fwd[i][2], m11 = s_fwd[i][3];
            float c0  = s_fwd[i][4], c1  = s_fwd[i][5];
            #pragma unroll
            for (int e = 0; e < EPT; ++e) {
                q[e] = fmaf(aw, tanh_fast(p[e]), q[e]);
                float nq = fmaf(m00, q[e], fmaf(m01, p[e], c0));
                float np = fmaf(m10, q[e], fmaf(m11, p[e], c1));
                q[e] = nq; p[e] = np;
            }
        }
        // layer i+1 (odd): p += aw*tanh(q), then affine
        {
            float aw = s_aw[i + 1];
            float m00 = s_fwd[i + 1][0], m01 = s_fwd[i + 1][1];
            float m10 = s_fwd[i + 1][2], m11 = s_fwd[i + 1][3];
            float c0  = s_fwd[i + 1][4], c1  = s_fwd[i + 1][5];
            #pragma unroll
            for (int e = 0; e < EPT; ++e) {
                p[e] = fmaf(aw, tanh_fast(q[e]), p[e]);
                float nq = fmaf(m00, q[e], fmaf(m01, p[e], c0));
                float np = fmaf(m10, q[e], fmaf(m11, p[e], c1));
                q[e] = nq; p[e] = np;
            }
        }
    }

    // time reversal
    #pragma unroll
    for (int e = 0; e < EPT; ++e) p[e] = -p[e];

    // ---------------- inverse chain ----------------
    #pragma unroll
    for (int i = N_LAYERS - 2; i >= 0; i -= 2) {
        // layer i+1 (odd): inverse affine, then p -= aw*tanh(q)
        {
            float aw = s_aw[i + 1];
            float u00 = s_inv[i + 1][0], u01 = s_inv[i + 1][1];
            float u10 = s_inv[i + 1][2], u11 = s_inv[i + 1][3];
            float d0  = s_inv[i + 1][4], d1  = s_inv[i + 1][5];
            #pragma unroll
            for (int e = 0; e < EPT; ++e) {
                float nq = fmaf(u00, q[e], fmaf(u01, p[e], d0));
                float np = fmaf(u10, q[e], fmaf(u11, p[e], d1));
                q[e] = nq; p[e] = np;
                p[e] = fmaf(-aw, tanh_fast(q[e]), p[e]);
            }
        }
        // layer i (even): inverse affine, then q -= aw*tanh(p)
        {
            float aw = s_aw[i];
            float u00 = s_inv[i][0], u01 = s_inv[i][1];
            float u10 = s_inv[i][2], u11 = s_inv[i][3];
            float d0  = s_inv[i][4], d1  = s_inv[i][5];
            #pragma unroll
            for (int e = 0; e < EPT; ++e) {
                float nq = fmaf(u00, q[e], fmaf(u01, p[e], d0));
                float np = fmaf(u10, q[e], fmaf(u11, p[e], d1));
                q[e] = nq; p[e] = np;
                q[e] = fmaf(-aw, tanh_fast(p[e]), q[e]);
            }
        }
    }

    #pragma unroll
    for (int e = 0; e < EPT; ++e) {
        int idx = base + e * TPB;
        if (idx < n) {
            out[idx] = make_float2(q[e], -p[e]);
        }
    }
}

extern "C" void kernel_launch(void* const* d_in, const int* in_sizes, int n_in,
                              void* d_out, int out_size)
{
    const float2* x     = (const float2*)d_in[0];
    const float*  act_w = (const float*)d_in[1];
    const float*  bias_b= (const float*)d_in[2];
    const float*  lin_w = (const float*)d_in[3];
    float2* out = (float2*)d_out;

    int n = in_sizes[0] / 2;   // number of (q,p) pairs

    int per_block = TPB * EPT;
    int blocks = (n + per_block - 1) / per_block;
    sympnet_kernel<<<blocks, TPB>>>(x, act_w, bias_b, lin_w, out, n);
}